// round 2
// baseline (speedup 1.0000x reference)
#include <cuda_runtime.h>
#include <cstdint>

#define N_POINTS   2097152
#define CTA_THREADS 64
#define TILE_PTS    64
#define NTILES     (N_POINTS / TILE_PTS)   // 32768
#define NBLOCKS    (148 * 6)               // persistent, 6 CTAs/SM by smem

// scratch geometry (floats)
#define FEAT_STRIDE 20
#define FEAT_FLOATS (32 * FEAT_STRIDE)     // 640
#define H1_STRIDE   68
#define H1_FLOATS   (16 * H1_STRIDE)       // 1088
#define SCR_FLOATS  (FEAT_FLOATS + H1_FLOATS)  // 1728 floats = 6912 B / warp

static __device__ __forceinline__ uint32_t f2tf(float f) {
    uint32_t r; asm("cvt.rna.tf32.f32 %0, %1;" : "=r"(r) : "f"(f)); return r;
}
static __device__ __forceinline__ float tfbits(float f) {
    return __uint_as_float(f2tf(f));
}

// m16n8k8 tf32 MMA, accumulate in place (D = A*B + D)
static __device__ __forceinline__ void mma8(float* d,
    uint32_t a0, uint32_t a1, uint32_t a2, uint32_t a3,
    uint32_t b0, uint32_t b1)
{
    asm volatile(
        "mma.sync.aligned.m16n8k8.row.col.f32.tf32.tf32.f32 "
        "{%0,%1,%2,%3}, {%4,%5,%6,%7}, {%8,%9}, {%0,%1,%2,%3};"
        : "+f"(d[0]), "+f"(d[1]), "+f"(d[2]), "+f"(d[3])
        : "r"(a0), "r"(a1), "r"(a2), "r"(a3), "r"(b0), "r"(b1));
}

__global__ void __launch_bounds__(CTA_THREADS, 6)
occ_mlp_kernel(const float* __restrict__ points, const float* __restrict__ grid,
               const float* __restrict__ W1, const float* __restrict__ b1,
               const float* __restrict__ W2, const float* __restrict__ b2,
               const float* __restrict__ W3, const float* __restrict__ b3,
               float* __restrict__ out)
{
    // B fragments, fragment-ordered: frag f = kt*8+nt, 64 floats each = [lane][2]
    __shared__ __align__(16) float sW1f[16 * 64];   // 4 KB
    __shared__ __align__(16) float sW2f[64 * 64];   // 16 KB
    __shared__ __align__(16) float sB1[64], sB2[64], sW3s[64];
    __shared__ float sB3v;
    __shared__ __align__(16) float sScr[2][SCR_FLOATS];  // per-warp scratch

    const int tid  = threadIdx.x;
    const int wid  = tid >> 5;
    const int lane = tid & 31;
    const int g    = lane >> 2;   // row group 0..7
    const int q    = lane & 3;    // quad index 0..3

    // ---- stage weights as tf32 B-fragments ----
    for (int i = tid; i < 16 * 64; i += CTA_THREADS) {
        int f = i >> 6, l2 = i & 63;
        int ln = l2 >> 1, r = l2 & 1;
        int kt = f >> 3, nt = f & 7;
        int k = kt * 8 + (ln & 3) + r * 4;
        int n = nt * 8 + (ln >> 2);
        sW1f[i] = tfbits(W1[n * 16 + k]);
    }
    for (int i = tid; i < 64 * 64; i += CTA_THREADS) {
        int f = i >> 6, l2 = i & 63;
        int ln = l2 >> 1, r = l2 & 1;
        int kt = f >> 3, nt = f & 7;
        int k = kt * 8 + (ln & 3) + r * 4;
        int n = nt * 8 + (ln >> 2);
        sW2f[i] = tfbits(W2[n * 64 + k]);
    }
    if (tid < 64) { sB1[tid] = b1[tid]; sB2[tid] = b2[tid]; sW3s[tid] = W3[tid]; }
    if (tid == 0) sB3v = b3[0];
    __syncthreads();

    float* scrF = sScr[wid];                // feats: 32 rows x stride 20
    float* scrH = sScr[wid] + FEAT_FLOATS;  // H1:    16 rows x stride 68

    for (int tile = blockIdx.x; tile < NTILES; tile += gridDim.x) {
        const int p0 = tile * TILE_PTS + wid * 32;
        const int p  = p0 + lane;

        // ---- gather: nearest grid cell, 16 fp32 feats ----
        const float x = __ldg(points + 3 * p);
        const float y = __ldg(points + 3 * p + 1);
        const float z = __ldg(points + 3 * p + 2);
        const int ix = (int)rintf(fminf(fmaxf(x * 127.0f, 0.0f), 127.0f));
        const int iy = (int)rintf(fminf(fmaxf(y * 127.0f, 0.0f), 127.0f));
        const int iz = (int)rintf(fminf(fmaxf(z * 127.0f, 0.0f), 127.0f));
        const float4* cell = (const float4*)grid
            + ((size_t)(((ix << 7) + iy) << 7) + iz) * 4;
        const float4 f0 = __ldg(cell + 0);
        const float4 f1 = __ldg(cell + 1);
        const float4 f2 = __ldg(cell + 2);
        const float4 f3 = __ldg(cell + 3);

        // store tf32-converted feats, row = lane (80B row => 16B-aligned float4)
        float* fr = scrF + lane * FEAT_STRIDE;
        ((float4*)fr)[0] = make_float4(tfbits(f0.x), tfbits(f0.y), tfbits(f0.z), tfbits(f0.w));
        ((float4*)fr)[1] = make_float4(tfbits(f1.x), tfbits(f1.y), tfbits(f1.z), tfbits(f1.w));
        ((float4*)fr)[2] = make_float4(tfbits(f2.x), tfbits(f2.y), tfbits(f2.z), tfbits(f2.w));
        ((float4*)fr)[3] = make_float4(tfbits(f3.x), tfbits(f3.y), tfbits(f3.z), tfbits(f3.w));
        __syncwarp();

#pragma unroll
        for (int rt = 0; rt < 2; rt++) {
            const int rbase = rt * 16;

            // ---- layer 1: feats[16x16] @ W1^T -> H1 tile [16x64] ----
            float acc[8][4];
#pragma unroll
            for (int nt = 0; nt < 8; nt++)
                acc[nt][0] = acc[nt][1] = acc[nt][2] = acc[nt][3] = 0.0f;

#pragma unroll
            for (int kt = 0; kt < 2; kt++) {
                const float* A = scrF + (rbase + g) * FEAT_STRIDE + kt * 8 + q;
                uint32_t a0 = __float_as_uint(A[0]);
                uint32_t a2 = __float_as_uint(A[4]);
                uint32_t a1 = __float_as_uint(A[8 * FEAT_STRIDE]);
                uint32_t a3 = __float_as_uint(A[8 * FEAT_STRIDE + 4]);
#pragma unroll
                for (int nt = 0; nt < 8; nt++) {
                    const float2 b = *(const float2*)(sW1f + (kt * 8 + nt) * 64 + lane * 2);
                    mma8(acc[nt], a0, a1, a2, a3,
                         __float_as_uint(b.x), __float_as_uint(b.y));
                }
            }

            // ---- bias + relu, write H1 (tf32 bits) ----
#pragma unroll
            for (int nt = 0; nt < 8; nt++) {
                const int c = nt * 8 + 2 * q;
                const float2 bb = *(const float2*)(sB1 + c);
                float v0 = fmaxf(acc[nt][0] + bb.x, 0.0f);
                float v1 = fmaxf(acc[nt][1] + bb.y, 0.0f);
                float v2 = fmaxf(acc[nt][2] + bb.x, 0.0f);
                float v3 = fmaxf(acc[nt][3] + bb.y, 0.0f);
                *(float2*)(scrH + g * H1_STRIDE + c)       = make_float2(tfbits(v0), tfbits(v1));
                *(float2*)(scrH + (g + 8) * H1_STRIDE + c) = make_float2(tfbits(v2), tfbits(v3));
            }
            __syncwarp();

            // ---- layer 2: H1[16x64] @ W2^T -> H2 tile [16x64] ----
            float acc2[8][4];
#pragma unroll
            for (int nt = 0; nt < 8; nt++)
                acc2[nt][0] = acc2[nt][1] = acc2[nt][2] = acc2[nt][3] = 0.0f;

#pragma unroll
            for (int kt = 0; kt < 8; kt++) {
                const float* A = scrH + g * H1_STRIDE + kt * 8 + q;
                uint32_t a0 = __float_as_uint(A[0]);
                uint32_t a2 = __float_as_uint(A[4]);
                uint32_t a1 = __float_as_uint(A[8 * H1_STRIDE]);
                uint32_t a3 = __float_as_uint(A[8 * H1_STRIDE + 4]);
#pragma unroll
                for (int nt = 0; nt < 8; nt++) {
                    const float2 b = *(const float2*)(sW2f + (kt * 8 + nt) * 64 + lane * 2);
                    mma8(acc2[nt], a0, a1, a2, a3,
                         __float_as_uint(b.x), __float_as_uint(b.y));
                }
            }
            __syncwarp();   // l2 reads done before next rt overwrites scrH

            // ---- layer 3: occ = tanh(relu(H2 + b2) . W3 + b3) ----
            float s0 = 0.0f, s1 = 0.0f;
#pragma unroll
            for (int nt = 0; nt < 8; nt++) {
                const int c = nt * 8 + 2 * q;
                const float2 bb = *(const float2*)(sB2 + c);
                const float2 ww = *(const float2*)(sW3s + c);
                s0 += fmaxf(acc2[nt][0] + bb.x, 0.0f) * ww.x
                    + fmaxf(acc2[nt][1] + bb.y, 0.0f) * ww.y;
                s1 += fmaxf(acc2[nt][2] + bb.x, 0.0f) * ww.x
                    + fmaxf(acc2[nt][3] + bb.y, 0.0f) * ww.y;
            }
            s0 += __shfl_xor_sync(0xFFFFFFFFu, s0, 1);
            s0 += __shfl_xor_sync(0xFFFFFFFFu, s0, 2);
            s1 += __shfl_xor_sync(0xFFFFFFFFu, s1, 1);
            s1 += __shfl_xor_sync(0xFFFFFFFFu, s1, 2);
            if (q == 0) {
                out[p0 + rbase + g]     = tanhf(s0 + sB3v);
                out[p0 + rbase + g + 8] = tanhf(s1 + sB3v);
            }
        }
    }
}

// ---------------- Launch ----------------
extern "C" void kernel_launch(void* const* d_in, const int* in_sizes, int n_in,
                              void* d_out, int out_size)
{
    const float* points = (const float*)d_in[0];
    const float* grid   = (const float*)d_in[1];
    const float* W1     = (const float*)d_in[2];
    const float* b1     = (const float*)d_in[3];
    const float* W2     = (const float*)d_in[4];
    const float* b2     = (const float*)d_in[5];
    const float* W3     = (const float*)d_in[6];
    const float* b3     = (const float*)d_in[7];

    occ_mlp_kernel<<<NBLOCKS, CTA_THREADS>>>(points, grid, W1, b1, W2, b2, W3, b3,
                                             (float*)d_out);
}

// round 3
// speedup vs baseline: 1.8249x; 1.8249x over previous
#include <cuda_runtime.h>
#include <cuda_fp16.h>
#include <cstdint>

#define N_POINTS    2097152
#define CTA_THREADS 64
#define TILE_PTS    64                      // 2 warps x 32 rows
#define NTILES      (N_POINTS / TILE_PTS)   // 32768
#define NBLOCKS     (148 * 8)               // persistent

// scratch strides (in halves) chosen for conflict-free A-frag LDS
#define FEAT_STRIDE 24     // 16 data + 8 pad  (12g+q distinct mod 32)
#define H1_STRIDE   72     // 64 data + 8 pad  (36g -> 4g mod 32)
#define SCR_HALVES  (32 * FEAT_STRIDE + 32 * H1_STRIDE)   // 3072 halves = 6KB/warp

static __device__ __forceinline__ uint32_t h2u(__half2 h) {
    return *reinterpret_cast<uint32_t*>(&h);
}
static __device__ __forceinline__ uint32_t pack_rn(float a, float b) {
    __half2 h = __floats2half2_rn(a, b);
    return h2u(h);
}

// m16n8k16 fp16 MMA, fp32 accumulate in place
static __device__ __forceinline__ void mma16(float* d, const uint32_t* a,
                                             uint32_t b0, uint32_t b1)
{
    asm volatile(
        "mma.sync.aligned.m16n8k16.row.col.f32.f16.f16.f32 "
        "{%0,%1,%2,%3}, {%4,%5,%6,%7}, {%8,%9}, {%0,%1,%2,%3};"
        : "+f"(d[0]), "+f"(d[1]), "+f"(d[2]), "+f"(d[3])
        : "r"(a[0]), "r"(a[1]), "r"(a[2]), "r"(a[3]), "r"(b0), "r"(b1));
}

__global__ void __launch_bounds__(CTA_THREADS, 8)
occ_mlp_kernel(const float* __restrict__ points, const float* __restrict__ grid,
               const float* __restrict__ W1, const float* __restrict__ b1,
               const float* __restrict__ W2, const float* __restrict__ b2,
               const float* __restrict__ W3, const float* __restrict__ b3,
               float* __restrict__ out)
{
    // fragment-ordered fp16 weights: frag f -> [32 lanes][2 regs(uint=half2)]
    __shared__ __align__(16) uint32_t sW1f[8 * 32 * 2];    // 2 KB  (kt=0 only)
    __shared__ __align__(16) uint32_t sW2f[32 * 32 * 2];   // 8 KB  (kt 0..3, nt 0..7)
    __shared__ __align__(16) float sB1[64], sB2[64], sW3s[64];
    __shared__ float sB3v;
    __shared__ __align__(16) unsigned short sScr[2][SCR_HALVES];  // 12 KB

    const int tid  = threadIdx.x;
    const int wid  = tid >> 5;
    const int lane = tid & 31;
    const int g    = lane >> 2;   // 0..7
    const int q    = lane & 3;    // 0..3

    // ---- stage weights as fp16 B-fragments (b0: k=2q..2q+1, b1: k=2q+8..2q+9; n = g) ----
    for (int i = tid; i < 8 * 32 * 2; i += CTA_THREADS) {
        int f = i >> 6, ln = (i >> 1) & 31, r = i & 1;
        int n = f * 8 + (ln >> 2);
        int k = 2 * (ln & 3) + 8 * r;
        sW1f[i] = pack_rn(W1[n * 16 + k], W1[n * 16 + k + 1]);
    }
    for (int i = tid; i < 32 * 32 * 2; i += CTA_THREADS) {
        int f = i >> 6, ln = (i >> 1) & 31, r = i & 1;
        int kt = f >> 3, nt = f & 7;
        int n = nt * 8 + (ln >> 2);
        int k = kt * 16 + 2 * (ln & 3) + 8 * r;
        sW2f[i] = pack_rn(W2[n * 64 + k], W2[n * 64 + k + 1]);
    }
    if (tid < 64) { sB1[tid] = b1[tid]; sB2[tid] = b2[tid]; sW3s[tid] = W3[tid]; }
    if (tid == 0) sB3v = b3[0];
    __syncthreads();

    unsigned short* scrF = sScr[wid];                    // 32 rows x 24 halves
    unsigned short* scrH = sScr[wid] + 32 * FEAT_STRIDE; // 32 rows x 72 halves

    for (int tile = blockIdx.x; tile < NTILES; tile += gridDim.x) {
        const int p0 = tile * TILE_PTS + wid * 32;
        const int p  = p0 + lane;

        // ---- gather: nearest grid cell, 16 fp32 feats -> fp16 row in SMEM ----
        const float x = __ldg(points + 3 * p);
        const float y = __ldg(points + 3 * p + 1);
        const float z = __ldg(points + 3 * p + 2);
        const int ix = (int)rintf(fminf(fmaxf(x * 127.0f, 0.0f), 127.0f));
        const int iy = (int)rintf(fminf(fmaxf(y * 127.0f, 0.0f), 127.0f));
        const int iz = (int)rintf(fminf(fmaxf(z * 127.0f, 0.0f), 127.0f));
        const float4* cell = (const float4*)grid
            + ((size_t)(((ix << 7) + iy) << 7) + iz) * 4;
        const float4 f0 = __ldg(cell + 0);
        const float4 f1 = __ldg(cell + 1);
        const float4 f2 = __ldg(cell + 2);
        const float4 f3 = __ldg(cell + 3);

        {
            uint4 u0, u1;
            u0.x = pack_rn(f0.x, f0.y); u0.y = pack_rn(f0.z, f0.w);
            u0.z = pack_rn(f1.x, f1.y); u0.w = pack_rn(f1.z, f1.w);
            u1.x = pack_rn(f2.x, f2.y); u1.y = pack_rn(f2.z, f2.w);
            u1.z = pack_rn(f3.x, f3.y); u1.w = pack_rn(f3.z, f3.w);
            *(uint4*)(scrF + lane * FEAT_STRIDE)     = u0;
            *(uint4*)(scrF + lane * FEAT_STRIDE + 8) = u1;
        }
        __syncwarp();

        // ---- layer 1: feats[32x16] @ W1^T -> H1 [32x64] (K=16 in one mma) ----
        uint32_t af[2][4];
#pragma unroll
        for (int rt = 0; rt < 2; rt++) {
            const unsigned short* A = scrF + (rt * 16 + g) * FEAT_STRIDE + 2 * q;
            af[rt][0] = *(const uint32_t*)(A);
            af[rt][1] = *(const uint32_t*)(A + 8 * FEAT_STRIDE);
            af[rt][2] = *(const uint32_t*)(A + 8);
            af[rt][3] = *(const uint32_t*)(A + 8 * FEAT_STRIDE + 8);
        }
        float acc1[2][8][4];
#pragma unroll
        for (int rt = 0; rt < 2; rt++)
#pragma unroll
            for (int nt = 0; nt < 8; nt++)
                acc1[rt][nt][0] = acc1[rt][nt][1] = acc1[rt][nt][2] = acc1[rt][nt][3] = 0.0f;
#pragma unroll
        for (int nt = 0; nt < 8; nt++) {
            const uint2 b = *(const uint2*)(sW1f + (nt * 32 + lane) * 2);
            mma16(acc1[0][nt], af[0], b.x, b.y);
            mma16(acc1[1][nt], af[1], b.x, b.y);
        }

        // ---- bias + relu -> H1 (fp16) ----
#pragma unroll
        for (int rt = 0; rt < 2; rt++) {
#pragma unroll
            for (int nt = 0; nt < 8; nt++) {
                const int c = nt * 8 + 2 * q;
                const float2 bb = *(const float2*)(sB1 + c);
                float v0 = fmaxf(acc1[rt][nt][0] + bb.x, 0.0f);
                float v1 = fmaxf(acc1[rt][nt][1] + bb.y, 0.0f);
                float v2 = fmaxf(acc1[rt][nt][2] + bb.x, 0.0f);
                float v3 = fmaxf(acc1[rt][nt][3] + bb.y, 0.0f);
                *(uint32_t*)(scrH + (rt * 16 + g)     * H1_STRIDE + c) = pack_rn(v0, v1);
                *(uint32_t*)(scrH + (rt * 16 + g + 8) * H1_STRIDE + c) = pack_rn(v2, v3);
            }
        }
        __syncwarp();

        // ---- layer 2: H1[32x64] @ W2^T -> H2 [32x64] (kt=4) ----
        float acc2[2][8][4];
#pragma unroll
        for (int rt = 0; rt < 2; rt++)
#pragma unroll
            for (int nt = 0; nt < 8; nt++)
                acc2[rt][nt][0] = acc2[rt][nt][1] = acc2[rt][nt][2] = acc2[rt][nt][3] = 0.0f;
#pragma unroll
        for (int kt = 0; kt < 4; kt++) {
            uint32_t a2[2][4];
#pragma unroll
            for (int rt = 0; rt < 2; rt++) {
                const unsigned short* A = scrH + (rt * 16 + g) * H1_STRIDE + kt * 16 + 2 * q;
                a2[rt][0] = *(const uint32_t*)(A);
                a2[rt][1] = *(const uint32_t*)(A + 8 * H1_STRIDE);
                a2[rt][2] = *(const uint32_t*)(A + 8);
                a2[rt][3] = *(const uint32_t*)(A + 8 * H1_STRIDE + 8);
            }
#pragma unroll
            for (int nt = 0; nt < 8; nt++) {
                const uint2 b = *(const uint2*)(sW2f + ((kt * 8 + nt) * 32 + lane) * 2);
                mma16(acc2[0][nt], a2[0], b.x, b.y);
                mma16(acc2[1][nt], a2[1], b.x, b.y);
            }
        }

        // ---- layer 3: occ = tanh(relu(H2 + b2) . W3 + b3) ----
        float s[4] = {0.0f, 0.0f, 0.0f, 0.0f};   // rows g, g+8, g+16, g+24
#pragma unroll
        for (int nt = 0; nt < 8; nt++) {
            const int c = nt * 8 + 2 * q;
            const float2 bb = *(const float2*)(sB2 + c);
            const float2 ww = *(const float2*)(sW3s + c);
            s[0] += fmaxf(acc2[0][nt][0] + bb.x, 0.0f) * ww.x
                  + fmaxf(acc2[0][nt][1] + bb.y, 0.0f) * ww.y;
            s[1] += fmaxf(acc2[0][nt][2] + bb.x, 0.0f) * ww.x
                  + fmaxf(acc2[0][nt][3] + bb.y, 0.0f) * ww.y;
            s[2] += fmaxf(acc2[1][nt][0] + bb.x, 0.0f) * ww.x
                  + fmaxf(acc2[1][nt][1] + bb.y, 0.0f) * ww.y;
            s[3] += fmaxf(acc2[1][nt][2] + bb.x, 0.0f) * ww.x
                  + fmaxf(acc2[1][nt][3] + bb.y, 0.0f) * ww.y;
        }
#pragma unroll
        for (int i = 0; i < 4; i++) {
            s[i] += __shfl_xor_sync(0xFFFFFFFFu, s[i], 1);
            s[i] += __shfl_xor_sync(0xFFFFFFFFu, s[i], 2);
        }
        if (q == 0) {
            out[p0 + g]      = tanhf(s[0] + sB3v);
            out[p0 + g + 8]  = tanhf(s[1] + sB3v);
            out[p0 + g + 16] = tanhf(s[2] + sB3v);
            out[p0 + g + 24] = tanhf(s[3] + sB3v);
        }
        __syncwarp();
    }
}

// ---------------- Launch ----------------
extern "C" void kernel_launch(void* const* d_in, const int* in_sizes, int n_in,
                              void* d_out, int out_size)
{
    const float* points = (const float*)d_in[0];
    const float* grid   = (const float*)d_in[1];
    const float* W1     = (const float*)d_in[2];
    const float* b1     = (const float*)d_in[3];
    const float* W2     = (const float*)d_in[4];
    const float* b2     = (const float*)d_in[5];
    const float* W3     = (const float*)d_in[6];
    const float* b3     = (const float*)d_in[7];

    occ_mlp_kernel<<<NBLOCKS, CTA_THREADS>>>(points, grid, W1, b1, W2, b2, W3, b3,
                                             (float*)d_out);
}

// round 4
// speedup vs baseline: 1.8255x; 1.0003x over previous
#include <cuda_runtime.h>
#include <cuda_fp16.h>
#include <cstdint>

#define N_POINTS    2097152
#define CTA_THREADS 64
#define TILE_PTS    64                      // 2 warps x 32 rows
#define NTILES      (N_POINTS / TILE_PTS)   // 32768
#define NBLOCKS     (148 * 6)               // persistent

// scratch strides (halves), conflict-free patterns
#define FEAT_STRIDE 24     // 16 data + 8 pad
#define H1_STRIDE   72     // 64 data + 8 pad
#define SCR_HALVES  (32 * FEAT_STRIDE + 32 * H1_STRIDE)   // 3072 halves = 6KB/warp

static __device__ __forceinline__ uint32_t pack_rn(float a, float b) {
    __half2 h = __floats2half2_rn(a, b);
    return *reinterpret_cast<uint32_t*>(&h);
}

// m16n8k16 fp16 MMA, fp32 accumulate in place
static __device__ __forceinline__ void mma16(float* d, const uint32_t* a,
                                             uint32_t b0, uint32_t b1)
{
    asm volatile(
        "mma.sync.aligned.m16n8k16.row.col.f32.f16.f16.f32 "
        "{%0,%1,%2,%3}, {%4,%5,%6,%7}, {%8,%9}, {%0,%1,%2,%3};"
        : "+f"(d[0]), "+f"(d[1]), "+f"(d[2]), "+f"(d[3])
        : "r"(a[0]), "r"(a[1]), "r"(a[2]), "r"(a[3]), "r"(b0), "r"(b1));
}

__global__ void __launch_bounds__(CTA_THREADS, 6)
occ_mlp_kernel(const float* __restrict__ points, const float* __restrict__ grid,
               const float* __restrict__ W1, const float* __restrict__ b1,
               const float* __restrict__ W2, const float* __restrict__ b2,
               const float* __restrict__ W3, const float* __restrict__ b3,
               float* __restrict__ out)
{
    __shared__ __align__(16) float sB1[64], sB2[64], sW3s[64];
    __shared__ float sB3v;
    __shared__ __align__(16) unsigned short sScr[2][SCR_HALVES];  // 12 KB

    const int tid  = threadIdx.x;
    const int wid  = tid >> 5;
    const int lane = tid & 31;
    const int g    = lane >> 2;   // 0..7
    const int q    = lane & 3;    // 0..3

    // ---- register-resident fp16 B-fragments (loop-invariant weights) ----
    // B-frag layout (m16n8k16 col): b0: k=2q..2q+1, b1: k=2q+8..2q+9, n=g
    uint2 w1f[8];
#pragma unroll
    for (int nt = 0; nt < 8; nt++) {
        const float* Wn = W1 + (nt * 8 + g) * 16;
        w1f[nt].x = pack_rn(Wn[2 * q],     Wn[2 * q + 1]);
        w1f[nt].y = pack_rn(Wn[2 * q + 8], Wn[2 * q + 9]);
    }
    uint2 w2f[4][8];
#pragma unroll
    for (int kt = 0; kt < 4; kt++)
#pragma unroll
        for (int nt = 0; nt < 8; nt++) {
            const float* Wn = W2 + (nt * 8 + g) * 64 + kt * 16 + 2 * q;
            w2f[kt][nt].x = pack_rn(Wn[0], Wn[1]);
            w2f[kt][nt].y = pack_rn(Wn[8], Wn[9]);
        }

    if (tid < 64) { sB1[tid] = b1[tid]; sB2[tid] = b2[tid]; sW3s[tid] = W3[tid]; }
    if (tid == 0) sB3v = b3[0];
    __syncthreads();

    unsigned short* scrF = sScr[wid];                    // 32 rows x 24 halves
    unsigned short* scrH = sScr[wid] + 32 * FEAT_STRIDE; // 32 rows x 72 halves

    const float4* cellbase = (const float4*)grid;

    for (int tile = blockIdx.x; tile < NTILES; tile += gridDim.x) {
        const int p0 = tile * TILE_PTS + wid * 32;
        const int p  = p0 + lane;

        // ---- compute own point's cell index ----
        const float x = __ldg(points + 3 * p);
        const float y = __ldg(points + 3 * p + 1);
        const float z = __ldg(points + 3 * p + 2);
        const int ix = (int)rintf(fminf(fmaxf(x * 127.0f, 0.0f), 127.0f));
        const int iy = (int)rintf(fminf(fmaxf(y * 127.0f, 0.0f), 127.0f));
        const int iz = (int)rintf(fminf(fmaxf(z * 127.0f, 0.0f), 127.0f));
        const uint32_t ci = (uint32_t)(((ix << 7) + iy) << 7) + (uint32_t)iz;

        // ---- quad-cooperative gather: 4 lanes fetch the 4 float4 of one cell ----
        // round r: point pp = r*8 + (lane>>2), segment q; 8 lines per LDG instead of 32
#pragma unroll
        for (int r = 0; r < 4; r++) {
            const int pp = r * 8 + g;
            const uint32_t cis = __shfl_sync(0xFFFFFFFFu, ci, pp);
            const float4 f = __ldg(cellbase + (size_t)cis * 4 + q);
            uint2 u;
            u.x = pack_rn(f.x, f.y);
            u.y = pack_rn(f.z, f.w);
            *(uint2*)(scrF + pp * FEAT_STRIDE + q * 4) = u;
        }
        __syncwarp();

        // ---- layer 1: feats[32x16] @ W1^T, nt-outer (small live acc) ----
        uint32_t af[2][4];
#pragma unroll
        for (int rt = 0; rt < 2; rt++) {
            const unsigned short* A = scrF + (rt * 16 + g) * FEAT_STRIDE + 2 * q;
            af[rt][0] = *(const uint32_t*)(A);
            af[rt][1] = *(const uint32_t*)(A + 8 * FEAT_STRIDE);
            af[rt][2] = *(const uint32_t*)(A + 8);
            af[rt][3] = *(const uint32_t*)(A + 8 * FEAT_STRIDE + 8);
        }
#pragma unroll
        for (int nt = 0; nt < 8; nt++) {
            float acc[2][4];
            acc[0][0] = acc[0][1] = acc[0][2] = acc[0][3] = 0.0f;
            acc[1][0] = acc[1][1] = acc[1][2] = acc[1][3] = 0.0f;
            mma16(acc[0], af[0], w1f[nt].x, w1f[nt].y);
            mma16(acc[1], af[1], w1f[nt].x, w1f[nt].y);
            const int c = nt * 8 + 2 * q;
            const float2 bb = *(const float2*)(sB1 + c);
#pragma unroll
            for (int rt = 0; rt < 2; rt++) {
                float v0 = fmaxf(acc[rt][0] + bb.x, 0.0f);
                float v1 = fmaxf(acc[rt][1] + bb.y, 0.0f);
                float v2 = fmaxf(acc[rt][2] + bb.x, 0.0f);
                float v3 = fmaxf(acc[rt][3] + bb.y, 0.0f);
                *(uint32_t*)(scrH + (rt * 16 + g)     * H1_STRIDE + c) = pack_rn(v0, v1);
                *(uint32_t*)(scrH + (rt * 16 + g + 8) * H1_STRIDE + c) = pack_rn(v2, v3);
            }
        }
        __syncwarp();

        // ---- layer 2 + 3 fused: preload all A2 frags, nt-outer, fold into dot ----
        uint32_t a2[2][4][4];
#pragma unroll
        for (int rt = 0; rt < 2; rt++)
#pragma unroll
            for (int kt = 0; kt < 4; kt++) {
                const unsigned short* A = scrH + (rt * 16 + g) * H1_STRIDE + kt * 16 + 2 * q;
                a2[rt][kt][0] = *(const uint32_t*)(A);
                a2[rt][kt][1] = *(const uint32_t*)(A + 8 * H1_STRIDE);
                a2[rt][kt][2] = *(const uint32_t*)(A + 8);
                a2[rt][kt][3] = *(const uint32_t*)(A + 8 * H1_STRIDE + 8);
            }

        float s[4] = {0.0f, 0.0f, 0.0f, 0.0f};   // rows g, g+8, g+16, g+24
#pragma unroll
        for (int nt = 0; nt < 8; nt++) {
            float acc[2][4];
            acc[0][0] = acc[0][1] = acc[0][2] = acc[0][3] = 0.0f;
            acc[1][0] = acc[1][1] = acc[1][2] = acc[1][3] = 0.0f;
#pragma unroll
            for (int kt = 0; kt < 4; kt++) {
                mma16(acc[0], a2[0][kt], w2f[kt][nt].x, w2f[kt][nt].y);
                mma16(acc[1], a2[1][kt], w2f[kt][nt].x, w2f[kt][nt].y);
            }
            const int c = nt * 8 + 2 * q;
            const float2 bb = *(const float2*)(sB2 + c);
            const float2 ww = *(const float2*)(sW3s + c);
            s[0] += fmaxf(acc[0][0] + bb.x, 0.0f) * ww.x
                  + fmaxf(acc[0][1] + bb.y, 0.0f) * ww.y;
            s[1] += fmaxf(acc[0][2] + bb.x, 0.0f) * ww.x
                  + fmaxf(acc[0][3] + bb.y, 0.0f) * ww.y;
            s[2] += fmaxf(acc[1][0] + bb.x, 0.0f) * ww.x
                  + fmaxf(acc[1][1] + bb.y, 0.0f) * ww.y;
            s[3] += fmaxf(acc[1][2] + bb.x, 0.0f) * ww.x
                  + fmaxf(acc[1][3] + bb.y, 0.0f) * ww.y;
        }
#pragma unroll
        for (int i = 0; i < 4; i++) {
            s[i] += __shfl_xor_sync(0xFFFFFFFFu, s[i], 1);
            s[i] += __shfl_xor_sync(0xFFFFFFFFu, s[i], 2);
        }
        if (q == 0) {
            out[p0 + g]      = tanhf(s[0] + sB3v);
            out[p0 + g + 8]  = tanhf(s[1] + sB3v);
            out[p0 + g + 16] = tanhf(s[2] + sB3v);
            out[p0 + g + 24] = tanhf(s[3] + sB3v);
        }
        __syncwarp();   // protect scrF/scrH against next-iteration overwrite
    }
}

// ---------------- Launch ----------------
extern "C" void kernel_launch(void* const* d_in, const int* in_sizes, int n_in,
                              void* d_out, int out_size)
{
    const float* points = (const float*)d_in[0];
    const float* grid   = (const float*)d_in[1];
    const float* W1     = (const float*)d_in[2];
    const float* b1     = (const float*)d_in[3];
    const float* W2     = (const float*)d_in[4];
    const float* b2     = (const float*)d_in[5];
    const float* W3     = (const float*)d_in[6];
    const float* b3     = (const float*)d_in[7];

    occ_mlp_kernel<<<NBLOCKS, CTA_THREADS>>>(points, grid, W1, b1, W2, b2, W3, b3,
                                             (float*)d_out);
}

// round 5
// speedup vs baseline: 2.2794x; 1.2487x over previous
#include <cuda_runtime.h>
#include <cuda_fp16.h>
#include <cstdint>

#define N_POINTS    2097152
#define CTA_THREADS 64
#define TILE_PTS    64                      // 2 warps x 32 rows
#define NTILES      (N_POINTS / TILE_PTS)   // 32768
#define NBLOCKS     (148 * 8)               // persistent

// scratch strides (halves), conflict-free patterns
#define FEAT_STRIDE 24     // 16 data + 8 pad
#define H1_STRIDE   72     // 64 data + 8 pad
#define SCR_HALVES  (32 * FEAT_STRIDE + 32 * H1_STRIDE)   // 3072 halves = 6KB/warp

static __device__ __forceinline__ uint32_t pack_rn(float a, float b) {
    __half2 h = __floats2half2_rn(a, b);
    return *reinterpret_cast<uint32_t*>(&h);
}

// m16n8k16 fp16 MMA, fp32 accumulate in place
static __device__ __forceinline__ void mma16(float* d, const uint32_t* a,
                                             uint32_t b0, uint32_t b1)
{
    asm volatile(
        "mma.sync.aligned.m16n8k16.row.col.f32.f16.f16.f32 "
        "{%0,%1,%2,%3}, {%4,%5,%6,%7}, {%8,%9}, {%0,%1,%2,%3};"
        : "+f"(d[0]), "+f"(d[1]), "+f"(d[2]), "+f"(d[3])
        : "r"(a[0]), "r"(a[1]), "r"(a[2]), "r"(a[3]), "r"(b0), "r"(b1));
}

// prefetch: point coords -> cell index -> quad-cooperative gather LDGs into regs
static __device__ __forceinline__ void gather_prefetch(
    const float* __restrict__ points, const float4* __restrict__ cellbase,
    int p, int g, int q, float4 f[4])
{
    const float x = __ldg(points + 3 * p);
    const float y = __ldg(points + 3 * p + 1);
    const float z = __ldg(points + 3 * p + 2);
    const int ix = (int)rintf(fminf(fmaxf(x * 127.0f, 0.0f), 127.0f));
    const int iy = (int)rintf(fminf(fmaxf(y * 127.0f, 0.0f), 127.0f));
    const int iz = (int)rintf(fminf(fmaxf(z * 127.0f, 0.0f), 127.0f));
    const uint32_t ci = (uint32_t)(((ix << 7) + iy) << 7) + (uint32_t)iz;
#pragma unroll
    for (int r = 0; r < 4; r++) {
        const uint32_t cis = __shfl_sync(0xFFFFFFFFu, ci, r * 8 + g);
        f[r] = __ldg(cellbase + (size_t)cis * 4 + q);
    }
}

__global__ void __launch_bounds__(CTA_THREADS, 8)
occ_mlp_kernel(const float* __restrict__ points, const float* __restrict__ grid,
               const float* __restrict__ W1, const float* __restrict__ b1,
               const float* __restrict__ W2, const float* __restrict__ b2,
               const float* __restrict__ W3, const float* __restrict__ b3,
               float* __restrict__ out)
{
    // W2 B-fragments in SMEM (shared across CTA): frag f=(kt*8+nt) -> [32 lanes] uint2
    __shared__ __align__(16) uint32_t sW2f[32 * 32 * 2];   // 8 KB
    __shared__ __align__(16) float sB1[64], sB2[64], sW3s[64];
    __shared__ float sB3v;
    __shared__ __align__(16) unsigned short sScr[2][SCR_HALVES];  // 12 KB

    const int tid  = threadIdx.x;
    const int wid  = tid >> 5;
    const int lane = tid & 31;
    const int g    = lane >> 2;   // 0..7
    const int q    = lane & 3;    // 0..3

    // ---- W1 B-fragments register-resident (small) ----
    uint2 w1f[8];
#pragma unroll
    for (int nt = 0; nt < 8; nt++) {
        const float* Wn = W1 + (nt * 8 + g) * 16;
        w1f[nt].x = pack_rn(Wn[2 * q],     Wn[2 * q + 1]);
        w1f[nt].y = pack_rn(Wn[2 * q + 8], Wn[2 * q + 9]);
    }
    // ---- stage W2 fragments into SMEM ----
    for (int i = tid; i < 32 * 32 * 2; i += CTA_THREADS) {
        int f = i >> 6, ln = (i >> 1) & 31, r = i & 1;
        int kt = f >> 3, nt = f & 7;
        int n = nt * 8 + (ln >> 2);
        int k = kt * 16 + 2 * (ln & 3) + 8 * r;
        sW2f[i] = pack_rn(W2[n * 64 + k], W2[n * 64 + k + 1]);
    }
    if (tid < 64) { sB1[tid] = b1[tid]; sB2[tid] = b2[tid]; sW3s[tid] = W3[tid]; }
    if (tid == 0) sB3v = b3[0];
    __syncthreads();

    unsigned short* scrF = sScr[wid];                    // 32 rows x 24 halves
    unsigned short* scrH = sScr[wid] + 32 * FEAT_STRIDE; // 32 rows x 72 halves

    const float4* cellbase = (const float4*)grid;

    // ---- prologue: prefetch first tile's gather ----
    float4 fcur[4];
    {
        const int t0 = blockIdx.x;
        if (t0 < NTILES)
            gather_prefetch(points, cellbase, t0 * TILE_PTS + wid * 32 + lane,
                            g, q, fcur);
    }

    for (int tile = blockIdx.x; tile < NTILES; tile += gridDim.x) {
        const int p0 = tile * TILE_PTS + wid * 32;

        // ---- commit current gather to SMEM (fp16) ----
#pragma unroll
        for (int r = 0; r < 4; r++) {
            const int pp = r * 8 + g;
            uint2 u;
            u.x = pack_rn(fcur[r].x, fcur[r].y);
            u.y = pack_rn(fcur[r].z, fcur[r].w);
            *(uint2*)(scrF + pp * FEAT_STRIDE + q * 4) = u;
        }

        // ---- issue NEXT tile's gather now (overlaps with MMA below) ----
        float4 fnext[4];
        const int ntile = tile + gridDim.x;
        if (ntile < NTILES)
            gather_prefetch(points, cellbase, ntile * TILE_PTS + wid * 32 + lane,
                            g, q, fnext);
        __syncwarp();

        // ---- layer 1: feats[32x16] @ W1^T, nt-outer ----
        uint32_t af[2][4];
#pragma unroll
        for (int rt = 0; rt < 2; rt++) {
            const unsigned short* A = scrF + (rt * 16 + g) * FEAT_STRIDE + 2 * q;
            af[rt][0] = *(const uint32_t*)(A);
            af[rt][1] = *(const uint32_t*)(A + 8 * FEAT_STRIDE);
            af[rt][2] = *(const uint32_t*)(A + 8);
            af[rt][3] = *(const uint32_t*)(A + 8 * FEAT_STRIDE + 8);
        }
#pragma unroll
        for (int nt = 0; nt < 8; nt++) {
            float acc[2][4];
            acc[0][0] = acc[0][1] = acc[0][2] = acc[0][3] = 0.0f;
            acc[1][0] = acc[1][1] = acc[1][2] = acc[1][3] = 0.0f;
            mma16(acc[0], af[0], w1f[nt].x, w1f[nt].y);
            mma16(acc[1], af[1], w1f[nt].x, w1f[nt].y);
            const int c = nt * 8 + 2 * q;
            const float2 bb = *(const float2*)(sB1 + c);
#pragma unroll
            for (int rt = 0; rt < 2; rt++) {
                float v0 = fmaxf(acc[rt][0] + bb.x, 0.0f);
                float v1 = fmaxf(acc[rt][1] + bb.y, 0.0f);
                float v2 = fmaxf(acc[rt][2] + bb.x, 0.0f);
                float v3 = fmaxf(acc[rt][3] + bb.y, 0.0f);
                *(uint32_t*)(scrH + (rt * 16 + g)     * H1_STRIDE + c) = pack_rn(v0, v1);
                *(uint32_t*)(scrH + (rt * 16 + g + 8) * H1_STRIDE + c) = pack_rn(v2, v3);
            }
        }
        __syncwarp();

        // ---- layer 2 + 3 fused ----
        uint32_t a2[2][4][4];
#pragma unroll
        for (int rt = 0; rt < 2; rt++)
#pragma unroll
            for (int kt = 0; kt < 4; kt++) {
                const unsigned short* A = scrH + (rt * 16 + g) * H1_STRIDE + kt * 16 + 2 * q;
                a2[rt][kt][0] = *(const uint32_t*)(A);
                a2[rt][kt][1] = *(const uint32_t*)(A + 8 * H1_STRIDE);
                a2[rt][kt][2] = *(const uint32_t*)(A + 8);
                a2[rt][kt][3] = *(const uint32_t*)(A + 8 * H1_STRIDE + 8);
            }

        float s[4] = {0.0f, 0.0f, 0.0f, 0.0f};   // rows g, g+8, g+16, g+24
#pragma unroll
        for (int nt = 0; nt < 8; nt++) {
            float acc[2][4];
            acc[0][0] = acc[0][1] = acc[0][2] = acc[0][3] = 0.0f;
            acc[1][0] = acc[1][1] = acc[1][2] = acc[1][3] = 0.0f;
#pragma unroll
            for (int kt = 0; kt < 4; kt++) {
                const uint2 b = *(const uint2*)(sW2f + ((kt * 8 + nt) * 32 + lane) * 2);
                mma16(acc[0], a2[0][kt], b.x, b.y);
                mma16(acc[1], a2[1][kt], b.x, b.y);
            }
            const int c = nt * 8 + 2 * q;
            const float2 bb = *(const float2*)(sB2 + c);
            const float2 ww = *(const float2*)(sW3s + c);
            s[0] += fmaxf(acc[0][0] + bb.x, 0.0f) * ww.x
                  + fmaxf(acc[0][1] + bb.y, 0.0f) * ww.y;
            s[1] += fmaxf(acc[0][2] + bb.x, 0.0f) * ww.x
                  + fmaxf(acc[0][3] + bb.y, 0.0f) * ww.y;
            s[2] += fmaxf(acc[1][0] + bb.x, 0.0f) * ww.x
                  + fmaxf(acc[1][1] + bb.y, 0.0f) * ww.y;
            s[3] += fmaxf(acc[1][2] + bb.x, 0.0f) * ww.x
                  + fmaxf(acc[1][3] + bb.y, 0.0f) * ww.y;
        }
#pragma unroll
        for (int i = 0; i < 4; i++) {
            s[i] += __shfl_xor_sync(0xFFFFFFFFu, s[i], 1);
            s[i] += __shfl_xor_sync(0xFFFFFFFFu, s[i], 2);
        }
        if (q == 0) {
            out[p0 + g]      = tanhf(s[0] + sB3v);
            out[p0 + g + 8]  = tanhf(s[1] + sB3v);
            out[p0 + g + 16] = tanhf(s[2] + sB3v);
            out[p0 + g + 24] = tanhf(s[3] + sB3v);
        }
        __syncwarp();   // scrF/scrH safe before next-iteration overwrite

#pragma unroll
        for (int r = 0; r < 4; r++) fcur[r] = fnext[r];
    }
}

// ---------------- Launch ----------------
extern "C" void kernel_launch(void* const* d_in, const int* in_sizes, int n_in,
                              void* d_out, int out_size)
{
    const float* points = (const float*)d_in[0];
    const float* grid   = (const float*)d_in[1];
    const float* W1     = (const float*)d_in[2];
    const float* b1     = (const float*)d_in[3];
    const float* W2     = (const float*)d_in[4];
    const float* b2     = (const float*)d_in[5];
    const float* W3     = (const float*)d_in[6];
    const float* b3     = (const float*)d_in[7];

    occ_mlp_kernel<<<NBLOCKS, CTA_THREADS>>>(points, grid, W1, b1, W2, b2, W3, b3,
                                             (float*)d_out);
}

// round 6
// speedup vs baseline: 2.6083x; 1.1443x over previous
#include <cuda_runtime.h>
#include <cuda_fp16.h>
#include <cstdint>

#define N_POINTS    2097152
#define CTA_THREADS 64
#define TILE_PTS    64                      // 2 warps x 32 rows
#define NTILES      (N_POINTS / TILE_PTS)   // 32768
#define NBLOCKS     (148 * 8)               // persistent

#define FEAT_STRIDE 24     // halves: 16 data + 8 pad, conflict-free
#define SCR_HALVES  (32 * FEAT_STRIDE)      // 768 halves = 1.5KB/warp

static __device__ __forceinline__ uint32_t pack_rn(float a, float b) {
    __half2 h = __floats2half2_rn(a, b);
    return *reinterpret_cast<uint32_t*>(&h);
}
static __device__ __forceinline__ __half2 u2h(uint32_t u) {
    return *reinterpret_cast<__half2*>(&u);
}
static __device__ __forceinline__ uint32_t h2u(__half2 h) {
    return *reinterpret_cast<uint32_t*>(&h);
}

// m16n8k16 fp16 MMA, fp32 accumulate in place
static __device__ __forceinline__ void mma16(float* d, const uint32_t* a,
                                             uint32_t b0, uint32_t b1)
{
    asm volatile(
        "mma.sync.aligned.m16n8k16.row.col.f32.f16.f16.f32 "
        "{%0,%1,%2,%3}, {%4,%5,%6,%7}, {%8,%9}, {%0,%1,%2,%3};"
        : "+f"(d[0]), "+f"(d[1]), "+f"(d[2]), "+f"(d[3])
        : "r"(a[0]), "r"(a[1]), "r"(a[2]), "r"(a[3]), "r"(b0), "r"(b1));
}

// m16n8k16 fp16 MMA, fp16 D, C = 0
static __device__ __forceinline__ void mma16_h(uint32_t* d, const uint32_t* a,
                                               uint32_t b0, uint32_t b1)
{
    asm volatile(
        "mma.sync.aligned.m16n8k16.row.col.f16.f16.f16.f16 "
        "{%0,%1}, {%2,%3,%4,%5}, {%6,%7}, {%8,%8};"
        : "=r"(d[0]), "=r"(d[1])
        : "r"(a[0]), "r"(a[1]), "r"(a[2]), "r"(a[3]), "r"(b0), "r"(b1), "r"(0u));
}

// prefetch: point coords -> cell index -> quad-cooperative gather LDGs into regs
static __device__ __forceinline__ void gather_prefetch(
    const float* __restrict__ points, const float4* __restrict__ cellbase,
    int p, int g, int q, float4 f[4])
{
    const float x = __ldg(points + 3 * p);
    const float y = __ldg(points + 3 * p + 1);
    const float z = __ldg(points + 3 * p + 2);
    const int ix = (int)rintf(fminf(fmaxf(x * 127.0f, 0.0f), 127.0f));
    const int iy = (int)rintf(fminf(fmaxf(y * 127.0f, 0.0f), 127.0f));
    const int iz = (int)rintf(fminf(fmaxf(z * 127.0f, 0.0f), 127.0f));
    const uint32_t ci = (uint32_t)(((ix << 7) + iy) << 7) + (uint32_t)iz;
#pragma unroll
    for (int r = 0; r < 4; r++) {
        const uint32_t cis = __shfl_sync(0xFFFFFFFFu, ci, r * 8 + g);
        f[r] = __ldg(cellbase + (size_t)cis * 4 + q);
    }
}

__global__ void __launch_bounds__(CTA_THREADS, 8)
occ_mlp_kernel(const float* __restrict__ points, const float* __restrict__ grid,
               const float* __restrict__ W1, const float* __restrict__ b1,
               const float* __restrict__ W2, const float* __restrict__ b2,
               const float* __restrict__ W3, const float* __restrict__ b3,
               float* __restrict__ out)
{
    // W2 B-fragments in SMEM: frag f=(kt*8+nt) -> [32 lanes] uint2
    __shared__ __align__(16) uint32_t sW2f[32 * 32 * 2];   // 8 KB
    __shared__ __align__(16) float sB2[64], sW3s[64];
    __shared__ float sB3v;
    __shared__ __align__(16) unsigned short sScr[2][SCR_HALVES];  // 3 KB

    const int tid  = threadIdx.x;
    const int wid  = tid >> 5;
    const int lane = tid & 31;
    const int g    = lane >> 2;   // 0..7
    const int q    = lane & 3;    // 0..3

    // ---- W1 B-fragments + layer-1 bias (half2) register-resident ----
    uint2 w1f[8];
    uint32_t b1h[8];
#pragma unroll
    for (int nt = 0; nt < 8; nt++) {
        const float* Wn = W1 + (nt * 8 + g) * 16;
        w1f[nt].x = pack_rn(Wn[2 * q],     Wn[2 * q + 1]);
        w1f[nt].y = pack_rn(Wn[2 * q + 8], Wn[2 * q + 9]);
        const int c = nt * 8 + 2 * q;
        b1h[nt] = pack_rn(b1[c], b1[c + 1]);
    }
    // ---- stage W2 fragments into SMEM ----
    for (int i = tid; i < 32 * 32 * 2; i += CTA_THREADS) {
        int f = i >> 6, ln = (i >> 1) & 31, r = i & 1;
        int kt = f >> 3, nt = f & 7;
        int n = nt * 8 + (ln >> 2);
        int k = kt * 16 + 2 * (ln & 3) + 8 * r;
        sW2f[i] = pack_rn(W2[n * 64 + k], W2[n * 64 + k + 1]);
    }
    if (tid < 64) { sB2[tid] = b2[tid]; sW3s[tid] = W3[tid]; }
    if (tid == 0) sB3v = b3[0];
    __syncthreads();

    unsigned short* scrF = sScr[wid];   // 32 rows x 24 halves
    const float4* cellbase = (const float4*)grid;
    const __half2 zero2 = __floats2half2_rn(0.0f, 0.0f);

    // ---- prologue: prefetch first tile's gather ----
    float4 fcur[4];
    if (blockIdx.x < NTILES)
        gather_prefetch(points, cellbase, blockIdx.x * TILE_PTS + wid * 32 + lane,
                        g, q, fcur);

    for (int tile = blockIdx.x; tile < NTILES; tile += gridDim.x) {
        const int p0 = tile * TILE_PTS + wid * 32;

        // ---- commit current gather to SMEM (fp16) ----
#pragma unroll
        for (int r = 0; r < 4; r++) {
            const int pp = r * 8 + g;
            uint2 u;
            u.x = pack_rn(fcur[r].x, fcur[r].y);
            u.y = pack_rn(fcur[r].z, fcur[r].w);
            *(uint2*)(scrF + pp * FEAT_STRIDE + q * 4) = u;
        }

        // ---- issue NEXT tile's gather (overlaps with MMA below) ----
        float4 fnext[4];
        const int ntile = tile + gridDim.x;
        if (ntile < NTILES)
            gather_prefetch(points, cellbase, ntile * TILE_PTS + wid * 32 + lane,
                            g, q, fnext);
        __syncwarp();

        // ---- layer-1 A-fragments ----
        uint32_t af[2][4];
#pragma unroll
        for (int rt = 0; rt < 2; rt++) {
            const unsigned short* A = scrF + (rt * 16 + g) * FEAT_STRIDE + 2 * q;
            af[rt][0] = *(const uint32_t*)(A);
            af[rt][1] = *(const uint32_t*)(A + 8 * FEAT_STRIDE);
            af[rt][2] = *(const uint32_t*)(A + 8);
            af[rt][3] = *(const uint32_t*)(A + 8 * FEAT_STRIDE + 8);
        }
        __syncwarp();   // af read done; scrF free for next-iter commit

        // ---- layer 1 (f16 D) -> layer-2 A-fragments ENTIRELY in registers ----
        // D-frag (rows g,g+8 / cols nt*8+2q,+1) == A-frag (rows g,g+8 / k=16kt+2q[+8])
        // at nt = 2kt (k-lo) and nt = 2kt+1 (k-hi). Pure relabeling, no SMEM.
        uint32_t a2r[2][4][4];   // [rt][kt][areg]
#pragma unroll
        for (int nt = 0; nt < 8; nt++) {
            const int kt = nt >> 1, hi = (nt & 1) * 2;
#pragma unroll
            for (int rt = 0; rt < 2; rt++) {
                uint32_t d[2];
                mma16_h(d, af[rt], w1f[nt].x, w1f[nt].y);
                a2r[rt][kt][hi]     = h2u(__hmax2(__hadd2(u2h(d[0]), u2h(b1h[nt])), zero2));
                a2r[rt][kt][hi + 1] = h2u(__hmax2(__hadd2(u2h(d[1]), u2h(b1h[nt])), zero2));
            }
        }

        // ---- layer 2 + 3 fused ----
        float s[4] = {0.0f, 0.0f, 0.0f, 0.0f};   // rows g, g+8, g+16, g+24
#pragma unroll
        for (int nt = 0; nt < 8; nt++) {
            float acc[2][4];
            acc[0][0] = acc[0][1] = acc[0][2] = acc[0][3] = 0.0f;
            acc[1][0] = acc[1][1] = acc[1][2] = acc[1][3] = 0.0f;
#pragma unroll
            for (int kt = 0; kt < 4; kt++) {
                const uint2 b = *(const uint2*)(sW2f + ((kt * 8 + nt) * 32 + lane) * 2);
                mma16(acc[0], a2r[0][kt], b.x, b.y);
                mma16(acc[1], a2r[1][kt], b.x, b.y);
            }
            const int c = nt * 8 + 2 * q;
            const float2 bb = *(const float2*)(sB2 + c);
            const float2 ww = *(const float2*)(sW3s + c);
            s[0] += fmaxf(acc[0][0] + bb.x, 0.0f) * ww.x
                  + fmaxf(acc[0][1] + bb.y, 0.0f) * ww.y;
            s[1] += fmaxf(acc[0][2] + bb.x, 0.0f) * ww.x
                  + fmaxf(acc[0][3] + bb.y, 0.0f) * ww.y;
            s[2] += fmaxf(acc[1][0] + bb.x, 0.0f) * ww.x
                  + fmaxf(acc[1][1] + bb.y, 0.0f) * ww.y;
            s[3] += fmaxf(acc[1][2] + bb.x, 0.0f) * ww.x
                  + fmaxf(acc[1][3] + bb.y, 0.0f) * ww.y;
        }
#pragma unroll
        for (int i = 0; i < 4; i++) {
            s[i] += __shfl_xor_sync(0xFFFFFFFFu, s[i], 1);
            s[i] += __shfl_xor_sync(0xFFFFFFFFu, s[i], 2);
        }
        if (q == 0) {
#pragma unroll
            for (int i = 0; i < 4; i++) {
                float v = fminf(fmaxf(s[i] + sB3v, -15.0f), 15.0f);
                float e = __expf(2.0f * v);
                out[p0 + g + i * 8] = __fdividef(e - 1.0f, e + 1.0f);
            }
        }

#pragma unroll
        for (int r = 0; r < 4; r++) fcur[r] = fnext[r];
    }
}

// ---------------- Launch ----------------
extern "C" void kernel_launch(void* const* d_in, const int* in_sizes, int n_in,
                              void* d_out, int out_size)
{
    const float* points = (const float*)d_in[0];
    const float* grid   = (const float*)d_in[1];
    const float* W1     = (const float*)d_in[2];
    const float* b1     = (const float*)d_in[3];
    const float* W2     = (const float*)d_in[4];
    const float* b2     = (const float*)d_in[5];
    const float* W3     = (const float*)d_in[6];
    const float* b3     = (const float*)d_in[7];

    occ_mlp_kernel<<<NBLOCKS, CTA_THREADS>>>(points, grid, W1, b1, W2, b2, W3, b3,
                                             (float*)d_out);
}